// round 1
// baseline (speedup 1.0000x reference)
#include <cuda_runtime.h>
#include <math.h>

#define NTHREADS 256
// Shared layout (floats)
#define OFF_W2A   0        // [66][64] = 4224
#define OFF_B2A   4224     // 64
#define OFF_W2B   4288     // [64][32] = 2048
#define OFF_B2B   6336     // 32
#define OFF_W2C   6368     // [32][32] = 1024
#define OFF_B2C   7392     // 32
#define OFF_NODE  7424     // [32][33] = 1056
#define OFF_H     8480     // [32][65] = 2080
#define OFF_MI    10560    // [32][35] = 1120
#define OFF_EDGE  11680    // [992][2] = 1984
#define OFF_SA    13664    // scratch A [32][68] = 2176
#define OFF_SB    15840    // scratch B [32][36] = 1152
#define SMEM_FLOATS 16992

__device__ __forceinline__ float gelu_f(float x) {
    return 0.5f * x * (1.0f + erff(x * 0.7071067811865476f));
}
__device__ __forceinline__ float sigm_f(float x) {
    return 1.0f / (1.0f + __expf(-x));
}

#define FMA8(acc, a, w0, w1) do { \
    acc[0] += (a) * (w0).x; acc[1] += (a) * (w0).y; \
    acc[2] += (a) * (w0).z; acc[3] += (a) * (w0).w; \
    acc[4] += (a) * (w1).x; acc[5] += (a) * (w1).y; \
    acc[6] += (a) * (w1).z; acc[7] += (a) * (w1).w; } while (0)

#define FMA4S(a0,a1,a2,a3, a, w) do { \
    a0 += (a) * (w).x; a1 += (a) * (w).y; \
    a2 += (a) * (w).z; a3 += (a) * (w).w; } while (0)

struct GnnParams {
    const float *node0, *edge, *h0, *mean, *vari;
    const int   *ujs, *iterp;
    const float *W1a, *b1a, *W2a, *b2a, *W2b, *b2b, *W2c, *b2c;
    const float *Wih, *Whh, *bih, *bhh, *W3b, *b3b;
    const float *W4a, *b4a, *W4b, *b4b, *W4c, *b4c, *W5a, *b5a, *W5b, *b5b;
    float *out;
};

__global__ __launch_bounds__(NTHREADS)
void gnn_kernel(GnnParams p) {
    extern __shared__ float sm[];
    const int tid = threadIdx.x;
    const int b   = blockIdx.x;

    float* sW2a  = sm + OFF_W2A;
    float* sb2a  = sm + OFF_B2A;
    float* sW2b  = sm + OFF_W2B;
    float* sb2b  = sm + OFF_B2B;
    float* sW2c  = sm + OFF_W2C;
    float* sb2c  = sm + OFF_B2C;
    float* sNode = sm + OFF_NODE;   // stride 33
    float* sH    = sm + OFF_H;      // stride 65
    float* sMi   = sm + OFF_MI;     // stride 35 (32 feats + mean + invv)
    float* sEdge = sm + OFF_EDGE;   // [992][2]
    float* sA    = sm + OFF_SA;     // scratch
    float* sB    = sm + OFF_SB;     // scratch

    // ---- cooperative init copies ----
    for (int i = tid; i < 66*64; i += NTHREADS) sW2a[i] = p.W2a[i];
    for (int i = tid; i < 64;    i += NTHREADS) sb2a[i] = p.b2a[i];
    for (int i = tid; i < 64*32; i += NTHREADS) sW2b[i] = p.W2b[i];
    for (int i = tid; i < 32;    i += NTHREADS) sb2b[i] = p.b2b[i];
    for (int i = tid; i < 32*32; i += NTHREADS) sW2c[i] = p.W2c[i];
    for (int i = tid; i < 32;    i += NTHREADS) sb2c[i] = p.b2c[i];
    for (int i = tid; i < 992*2; i += NTHREADS) sEdge[i] = p.edge[b*1984 + i];
    for (int i = tid; i < 32*64; i += NTHREADS) {
        int n = i >> 6, k = i & 63;
        sH[n*65 + k] = p.h0[b*2048 + i];
    }
    for (int i = tid; i < 32*32; i += NTHREADS) {
        int n = i >> 5, k = i & 31;
        sA[n*33 + k] = p.node0[b*1024 + i];
    }
    if (tid < 32) {
        sMi[tid*35 + 32] = p.mean[b*32 + tid];
        sMi[tid*35 + 33] = 1.0f / p.vari[b*32 + tid];
    }
    __syncthreads();

    // ---- node = node0 @ W1a + b1a ----
    {
        const int n = tid >> 3, f0 = (tid & 7) << 2;
        float a0 = p.b1a[f0], a1 = p.b1a[f0+1], a2 = p.b1a[f0+2], a3 = p.b1a[f0+3];
        const float* r = sA + n*33;
        #pragma unroll 8
        for (int k = 0; k < 32; ++k) {
            float a = r[k];
            float4 w = *(const float4*)(p.W1a + k*32 + f0);
            FMA4S(a0,a1,a2,a3, a, w);
        }
        float* o = sNode + n*33 + f0;
        o[0]=a0; o[1]=a1; o[2]=a2; o[3]=a3;
    }
    __syncthreads();

    const int iters = p.iterp ? *p.iterp : 3;
    const int ty = tid >> 3, tx = tid & 7;

    for (int it = 0; it < iters; ++it) {
        for (int i = 0; i < 32; ++i) {
            // ---- layer 1: per-node tile, 31 edges x 64 out (in = 66) ----
            if (ty < 31) {
                const int e  = i*31 + ty;
                const int jn = p.ujs[e];
                const int f0 = tx << 3;
                float acc[8];
                #pragma unroll
                for (int o = 0; o < 8; ++o) acc[o] = sb2a[f0 + o];
                const float* ni = sNode + i*33;
                const float* nj = sNode + jn*33;
                #pragma unroll 8
                for (int k = 0; k < 32; ++k) {
                    float a = ni[k];
                    float4 w0 = *(const float4*)(sW2a + k*64 + f0);
                    float4 w1 = *(const float4*)(sW2a + k*64 + f0 + 4);
                    FMA8(acc, a, w0, w1);
                }
                #pragma unroll 8
                for (int k = 0; k < 32; ++k) {
                    float a = nj[k];
                    float4 w0 = *(const float4*)(sW2a + (k+32)*64 + f0);
                    float4 w1 = *(const float4*)(sW2a + (k+32)*64 + f0 + 4);
                    FMA8(acc, a, w0, w1);
                }
                #pragma unroll
                for (int k = 0; k < 2; ++k) {
                    float a = sEdge[e*2 + k];
                    float4 w0 = *(const float4*)(sW2a + (k+64)*64 + f0);
                    float4 w1 = *(const float4*)(sW2a + (k+64)*64 + f0 + 4);
                    FMA8(acc, a, w0, w1);
                }
                float4 o0 = make_float4(gelu_f(acc[0]), gelu_f(acc[1]),
                                        gelu_f(acc[2]), gelu_f(acc[3]));
                float4 o1 = make_float4(gelu_f(acc[4]), gelu_f(acc[5]),
                                        gelu_f(acc[6]), gelu_f(acc[7]));
                *(float4*)(sA + ty*68 + f0)     = o0;
                *(float4*)(sA + ty*68 + f0 + 4) = o1;
            }
            __syncthreads();

            // ---- layer 2: 64 -> 32 ----
            if (ty < 31) {
                const int f0 = tx << 2;
                float a0 = sb2b[f0], a1 = sb2b[f0+1], a2 = sb2b[f0+2], a3 = sb2b[f0+3];
                const float* r = sA + ty*68;
                #pragma unroll 8
                for (int k = 0; k < 64; ++k) {
                    float a = r[k];
                    float4 w = *(const float4*)(sW2b + k*32 + f0);
                    FMA4S(a0,a1,a2,a3, a, w);
                }
                *(float4*)(sB + ty*36 + f0) =
                    make_float4(gelu_f(a0), gelu_f(a1), gelu_f(a2), gelu_f(a3));
            }
            __syncthreads();

            // ---- layer 3: 32 -> 32 (m3 into sA, stride 36) ----
            if (ty < 31) {
                const int f0 = tx << 2;
                float a0 = sb2c[f0], a1 = sb2c[f0+1], a2 = sb2c[f0+2], a3 = sb2c[f0+3];
                const float* r = sB + ty*36;
                #pragma unroll 8
                for (int k = 0; k < 32; ++k) {
                    float a = r[k];
                    float4 w = *(const float4*)(sW2c + k*32 + f0);
                    FMA4S(a0,a1,a2,a3, a, w);
                }
                *(float4*)(sA + ty*36 + f0) =
                    make_float4(gelu_f(a0), gelu_f(a1), gelu_f(a2), gelu_f(a3));
            }
            __syncthreads();

            // ---- segment sum over 31 edges -> m_i[i][0:32] ----
            {
                const int f = tid & 31, c = tid >> 5;   // c in 0..7
                float s = 0.f;
                for (int e2 = c; e2 < 31; e2 += 8) s += sA[e2*36 + f];
                sB[c*33 + f] = s;
            }
            __syncthreads();
            if (tid < 32) {
                float s = 0.f;
                #pragma unroll
                for (int c = 0; c < 8; ++c) s += sB[c*33 + tid];
                sMi[i*35 + tid] = s;
            }
            // next tile's first __syncthreads protects reuse of sA/sB
        }
        __syncthreads();

        // ---- GRU cell (GELU new gate) ----
        {
            const int n  = ty;
            const int c0 = tx << 3;
            float ar[8], az[8], an_[8], hn_[8];
            #pragma unroll
            for (int o = 0; o < 8; ++o) {
                ar[o]  = p.bih[c0+o]      + p.bhh[c0+o];
                az[o]  = p.bih[64+c0+o]   + p.bhh[64+c0+o];
                an_[o] = p.bih[128+c0+o];
                hn_[o] = p.bhh[128+c0+o];
            }
            const float* mi = sMi + n*35;
            #pragma unroll 2
            for (int k = 0; k < 34; ++k) {
                float a = mi[k];
                const float* w = p.Wih + k*192;
                float4 r0 = *(const float4*)(w + c0);
                float4 r1 = *(const float4*)(w + c0 + 4);
                float4 z0 = *(const float4*)(w + 64 + c0);
                float4 z1 = *(const float4*)(w + 64 + c0 + 4);
                float4 n0 = *(const float4*)(w + 128 + c0);
                float4 n1 = *(const float4*)(w + 128 + c0 + 4);
                FMA8(ar, a, r0, r1);
                FMA8(az, a, z0, z1);
                FMA8(an_, a, n0, n1);
            }
            const float* hv = sH + n*65;
            #pragma unroll 2
            for (int k = 0; k < 64; ++k) {
                float a = hv[k];
                const float* w = p.Whh + k*192;
                float4 r0 = *(const float4*)(w + c0);
                float4 r1 = *(const float4*)(w + c0 + 4);
                float4 z0 = *(const float4*)(w + 64 + c0);
                float4 z1 = *(const float4*)(w + 64 + c0 + 4);
                float4 n0 = *(const float4*)(w + 128 + c0);
                float4 n1 = *(const float4*)(w + 128 + c0 + 4);
                FMA8(ar, a, r0, r1);
                FMA8(az, a, z0, z1);
                FMA8(hn_, a, n0, n1);
            }
            float hnew[8];
            #pragma unroll
            for (int o = 0; o < 8; ++o) {
                float r = sigm_f(ar[o]);
                float z = sigm_f(az[o]);
                float g = gelu_f(an_[o] + r * hn_[o]);
                float hold = hv[c0 + o];
                hnew[o] = (1.0f - z) * g + z * hold;
            }
            __syncthreads();
            #pragma unroll
            for (int o = 0; o < 8; ++o) sH[n*65 + c0 + o] = hnew[o];
        }
        __syncthreads();

        // ---- node = h @ W3b + b3b ----
        {
            const int n = ty, f0 = tx << 2;
            float a0 = p.b3b[f0], a1 = p.b3b[f0+1], a2 = p.b3b[f0+2], a3 = p.b3b[f0+3];
            const float* hv = sH + n*65;
            #pragma unroll 8
            for (int k = 0; k < 64; ++k) {
                float a = hv[k];
                float4 w = *(const float4*)(p.W3b + k*32 + f0);
                FMA4S(a0,a1,a2,a3, a, w);
            }
            float* o = sNode + n*33 + f0;
            o[0]=a0; o[1]=a1; o[2]=a2; o[3]=a3;
        }
        __syncthreads();
    }

    // ---- readout: node -> W4a -> W4b -> W4c -> W5a -> W5b (no activations) ----
    {   // t1 = node @ W4a + b4a : [32][64] into sA (stride 68)
        const int n = ty, f0 = tx << 3;
        float acc[8];
        #pragma unroll
        for (int o = 0; o < 8; ++o) acc[o] = p.b4a[f0 + o];
        const float* r = sNode + n*33;
        #pragma unroll 8
        for (int k = 0; k < 32; ++k) {
            float a = r[k];
            float4 w0 = *(const float4*)(p.W4a + k*64 + f0);
            float4 w1 = *(const float4*)(p.W4a + k*64 + f0 + 4);
            FMA8(acc, a, w0, w1);
        }
        #pragma unroll
        for (int o = 0; o < 8; ++o) sA[n*68 + f0 + o] = acc[o];
    }
    __syncthreads();
    {   // t2 = t1 @ W4b + b4b : [32][32] into sB (stride 36)
        const int n = ty, f0 = tx << 2;
        float a0 = p.b4b[f0], a1 = p.b4b[f0+1], a2 = p.b4b[f0+2], a3 = p.b4b[f0+3];
        const float* r = sA + n*68;
        #pragma unroll 8
        for (int k = 0; k < 64; ++k) {
            float a = r[k];
            float4 w = *(const float4*)(p.W4b + k*32 + f0);
            FMA4S(a0,a1,a2,a3, a, w);
        }
        float* o = sB + n*36 + f0;
        o[0]=a0; o[1]=a1; o[2]=a2; o[3]=a3;
    }
    __syncthreads();
    {   // t3 = t2 @ W4c + b4c : [32][32] into sA (stride 36)
        const int n = ty, f0 = tx << 2;
        float a0 = p.b4c[f0], a1 = p.b4c[f0+1], a2 = p.b4c[f0+2], a3 = p.b4c[f0+3];
        const float* r = sB + n*36;
        #pragma unroll 8
        for (int k = 0; k < 32; ++k) {
            float a = r[k];
            float4 w = *(const float4*)(p.W4c + k*32 + f0);
            FMA4S(a0,a1,a2,a3, a, w);
        }
        float* o = sA + n*36 + f0;
        o[0]=a0; o[1]=a1; o[2]=a2; o[3]=a3;
    }
    __syncthreads();
    {   // t4 = t3 @ W5a + b5a : [32][16] into sB (stride 18)
        const int n = ty, f0 = tx << 1;
        float a0 = p.b5a[f0], a1 = p.b5a[f0 + 1];
        const float* r = sA + n*36;
        #pragma unroll 8
        for (int k = 0; k < 32; ++k) {
            float a = r[k];
            a0 += a * p.W5a[k*16 + f0];
            a1 += a * p.W5a[k*16 + f0 + 1];
        }
        sB[n*18 + f0]     = a0;
        sB[n*18 + f0 + 1] = a1;
    }
    __syncthreads();
    if (tid < 64) {   // R = t4 @ W5b + b5b ; outputs (R0, 1/R1)
        const int n = tid >> 1, col = tid & 1;
        float acc = p.b5b[col];
        const float* r = sB + n*18;
        #pragma unroll
        for (int k = 0; k < 16; ++k) acc += r[k] * p.W5b[k*2 + col];
        if (col == 0) p.out[b*32 + n] = acc;
        else          p.out[32768 + b*32 + n] = 1.0f / acc;
    }
}

extern "C" void kernel_launch(void* const* d_in, const int* in_sizes, int n_in,
                              void* d_out, int out_size) {
    // Inputs (metadata order): node0, edge, h, node_mean, node_vari, u_is, u_js,
    // [iter_num], W1a,b1a, W2a,b2a, W2b,b2b, W2c,b2c, Wih,Whh,bih,bhh, W3b,b3b,
    // W4a,b4a, W4b,b4b, W4c,b4c, W5a,b5a, W5b,b5b
    const int has_iter = (n_in >= 32) ? 1 : 0;
    const int base = has_iter ? 8 : 7;

    GnnParams p;
    p.node0 = (const float*)d_in[0];
    p.edge  = (const float*)d_in[1];
    p.h0    = (const float*)d_in[2];
    p.mean  = (const float*)d_in[3];
    p.vari  = (const float*)d_in[4];
    p.ujs   = (const int*)d_in[6];
    p.iterp = has_iter ? (const int*)d_in[7] : nullptr;
    p.W1a = (const float*)d_in[base+0];  p.b1a = (const float*)d_in[base+1];
    p.W2a = (const float*)d_in[base+2];  p.b2a = (const float*)d_in[base+3];
    p.W2b = (const float*)d_in[base+4];  p.b2b = (const float*)d_in[base+5];
    p.W2c = (const float*)d_in[base+6];  p.b2c = (const float*)d_in[base+7];
    p.Wih = (const float*)d_in[base+8];  p.Whh = (const float*)d_in[base+9];
    p.bih = (const float*)d_in[base+10]; p.bhh = (const float*)d_in[base+11];
    p.W3b = (const float*)d_in[base+12]; p.b3b = (const float*)d_in[base+13];
    p.W4a = (const float*)d_in[base+14]; p.b4a = (const float*)d_in[base+15];
    p.W4b = (const float*)d_in[base+16]; p.b4b = (const float*)d_in[base+17];
    p.W4c = (const float*)d_in[base+18]; p.b4c = (const float*)d_in[base+19];
    p.W5a = (const float*)d_in[base+20]; p.b5a = (const float*)d_in[base+21];
    p.W5b = (const float*)d_in[base+22]; p.b5b = (const float*)d_in[base+23];
    p.out = (float*)d_out;

    cudaFuncSetAttribute(gnn_kernel,
                         cudaFuncAttributeMaxDynamicSharedMemorySize,
                         SMEM_FLOATS * (int)sizeof(float));
    gnn_kernel<<<1024, NTHREADS, SMEM_FLOATS * sizeof(float)>>>(p);
}

// round 2
// speedup vs baseline: 2.6199x; 2.6199x over previous
#include <cuda_runtime.h>
#include <math.h>

#define NT 256
#define ST 132   // edge-buffer row stride (128 slots + 4 pad)

// Shared layout (float offsets)
#define OFF_W2A   0        // [66][64] = 4224
#define OFF_B2A   4224     // 64
#define OFF_W2B   4288     // [64][32] = 2048
#define OFF_B2B   6336     // 32
#define OFF_W2C   6368     // [32][32] = 1024
#define OFF_B2C   7392     // 32
#define OFF_NT    7424     // nodeT [32 feat][32 node] stride 33 = 1056
#define OFF_H     8480     // [32][65] = 2080
#define OFF_MI    10560    // [32][35] = 1120
#define OFF_JS    11680    // 992 ints
#define OFF_BASE  12672    // [4][64] = 256
#define OFF_A     12928    // bufA: uT [34][132]=4488 / m2T [32][132]
#define OFF_B     17416    // bufB: m1T [64][132]=8448 / m3T [32][132]
#define SMEM_FLOATS 25864  // 103,456 B -> 2 CTAs/SM

__device__ __forceinline__ float gelu_f(float x) {
    return 0.5f * x * (1.0f + erff(x * 0.7071067811865476f));
}
__device__ __forceinline__ float sigm_f(float x) {
    return 1.0f / (1.0f + __expf(-x));
}

#define FMA8(acc, a, w0, w1) do { \
    acc[0] += (a) * (w0).x; acc[1] += (a) * (w0).y; \
    acc[2] += (a) * (w0).z; acc[3] += (a) * (w0).w; \
    acc[4] += (a) * (w1).x; acc[5] += (a) * (w1).y; \
    acc[6] += (a) * (w1).z; acc[7] += (a) * (w1).w; } while (0)

struct GnnParams {
    const float *node0, *edge, *h0, *mean, *vari;
    const int   *ujs, *iterp;
    const float *W1a, *b1a, *W2a, *b2a, *W2b, *b2b, *W2c, *b2c;
    const float *Wih, *Whh, *bih, *bhh, *W3b, *b3b;
    const float *W4a, *b4a, *W4b, *b4b, *W4c, *b4c, *W5a, *b5a, *W5b, *b5b;
    float *out;
};

// Build uT (34 x 128: node_j feats rows 0..31, edge feats rows 32,33) and
// per-node base = node_i @ W2a[0:32] + b2a for one 4-node chunk.
__device__ __forceinline__ void build_chunk(
    int c, int tid, int b, const float* __restrict__ edge_g,
    float* uT, const float* sNT, const int* sJs,
    const float* sW2a, const float* sb2a, float* sBase)
{
    const int ce0 = c * 124;
    for (int idx = tid; idx < 34 * 128; idx += NT) {
        const int k = idx >> 7, e = idx & 127;
        float v;
        if (k < 32) {
            const int j = (e < 124) ? sJs[ce0 + e] : 0;
            v = sNT[k * 33 + j];
        } else {
            v = (e < 124) ? edge_g[(ce0 + e) * 2 + (k - 32)] : 0.0f;
        }
        uT[k * ST + e] = v;
    }
    {   // base[n2][cc], 4 nodes x 64 cols, one cell per thread
        const int n2 = tid >> 6, cc = tid & 63;
        const int ni = c * 4 + n2;
        float acc = sb2a[cc];
        #pragma unroll 8
        for (int k = 0; k < 32; ++k)
            acc += sNT[k * 33 + ni] * sW2a[k * 64 + cc];
        sBase[n2 * 64 + cc] = acc;
    }
}

__global__ __launch_bounds__(NT)
void gnn_kernel(GnnParams p) {
    extern __shared__ float sm[];
    const int tid = threadIdx.x;
    const int b   = blockIdx.x;

    float* sW2a  = sm + OFF_W2A;
    float* sb2a  = sm + OFF_B2A;
    float* sW2b  = sm + OFF_W2B;
    float* sb2b  = sm + OFF_B2B;
    float* sW2c  = sm + OFF_W2C;
    float* sb2c  = sm + OFF_B2C;
    float* sNT   = sm + OFF_NT;    // node^T [feat][node], stride 33
    float* sH    = sm + OFF_H;     // stride 65
    float* sMi   = sm + OFF_MI;    // stride 35
    int*   sJs   = (int*)(sm + OFF_JS);
    float* sBase = sm + OFF_BASE;
    float* bufA  = sm + OFF_A;
    float* bufB  = sm + OFF_B;
    const float* edge_g = p.edge + b * 1984;

    // ---- init copies ----
    for (int i = tid; i < 66*64; i += NT) sW2a[i] = p.W2a[i];
    for (int i = tid; i < 64;    i += NT) sb2a[i] = p.b2a[i];
    for (int i = tid; i < 64*32; i += NT) sW2b[i] = p.W2b[i];
    for (int i = tid; i < 32;    i += NT) sb2b[i] = p.b2b[i];
    for (int i = tid; i < 32*32; i += NT) sW2c[i] = p.W2c[i];
    for (int i = tid; i < 32;    i += NT) sb2c[i] = p.b2c[i];
    for (int i = tid; i < 992;   i += NT) sJs[i]  = p.ujs[i];
    for (int i = tid; i < 32*64; i += NT) {
        int n = i >> 6, k = i & 63;
        sH[n*65 + k] = p.h0[b*2048 + i];
    }
    for (int i = tid; i < 1024; i += NT) bufB[i] = p.node0[b*1024 + i];
    if (tid < 32) {
        sMi[tid*35 + 32] = p.mean[b*32 + tid];
        sMi[tid*35 + 33] = 1.0f / p.vari[b*32 + tid];
    }
    __syncthreads();

    // ---- node = node0 @ W1a + b1a (write transposed into sNT) ----
    {
        const int n = tid >> 3, f0 = (tid & 7) << 2;
        float a0 = p.b1a[f0], a1 = p.b1a[f0+1], a2 = p.b1a[f0+2], a3 = p.b1a[f0+3];
        const float* r = bufB + n*32;
        #pragma unroll 8
        for (int k = 0; k < 32; ++k) {
            float a = r[k];
            float4 w = *(const float4*)(p.W1a + k*32 + f0);
            a0 += a*w.x; a1 += a*w.y; a2 += a*w.z; a3 += a*w.w;
        }
        sNT[(f0+0)*33 + n] = a0; sNT[(f0+1)*33 + n] = a1;
        sNT[(f0+2)*33 + n] = a2; sNT[(f0+3)*33 + n] = a3;
    }
    __syncthreads();

    const int iters = p.iterp ? *p.iterp : 3;

    for (int it = 0; it < iters; ++it) {
        float* uT  = bufA;   // [34][ST]
        float* m1T = bufB;   // [64][ST]
        float* m2T = bufA;   // [32][ST] (overwrites uT after L1)
        float* m3T = bufB;   // [32][ST] (overwrites m1T after L2)

        build_chunk(0, tid, b, edge_g, uT, sNT, sJs, sW2a, sb2a, sBase);
        __syncthreads();

        for (int c = 0; c < 8; ++c) {
            // ---- Layer 1 (j+edge part): [34k][128e] x W2a[32:66] -> m1T ----
            {
                const int cg = tid & 15, eg = tid >> 4;
                const int e0 = eg*8, c0 = cg*4;
                float acc[8][4];
                #pragma unroll
                for (int ei = 0; ei < 8; ++ei) {
                    int e = e0 + ei;
                    int n2 = (e * 2115) >> 16; if (n2 > 3) n2 = 3;
                    float4 bv = *(const float4*)(sBase + n2*64 + c0);
                    acc[ei][0] = bv.x; acc[ei][1] = bv.y;
                    acc[ei][2] = bv.z; acc[ei][3] = bv.w;
                }
                #pragma unroll 2
                for (int k = 0; k < 34; ++k) {
                    float4 a0 = *(const float4*)(uT + k*ST + e0);
                    float4 a1 = *(const float4*)(uT + k*ST + e0 + 4);
                    float4 w  = *(const float4*)(sW2a + (32+k)*64 + c0);
                    float av[8] = {a0.x,a0.y,a0.z,a0.w,a1.x,a1.y,a1.z,a1.w};
                    #pragma unroll
                    for (int ei = 0; ei < 8; ++ei) {
                        acc[ei][0] += av[ei]*w.x; acc[ei][1] += av[ei]*w.y;
                        acc[ei][2] += av[ei]*w.z; acc[ei][3] += av[ei]*w.w;
                    }
                }
                #pragma unroll
                for (int ci = 0; ci < 4; ++ci) {
                    float4 o0 = make_float4(gelu_f(acc[0][ci]), gelu_f(acc[1][ci]),
                                            gelu_f(acc[2][ci]), gelu_f(acc[3][ci]));
                    float4 o1 = make_float4(gelu_f(acc[4][ci]), gelu_f(acc[5][ci]),
                                            gelu_f(acc[6][ci]), gelu_f(acc[7][ci]));
                    *(float4*)(m1T + (c0+ci)*ST + e0)     = o0;
                    *(float4*)(m1T + (c0+ci)*ST + e0 + 4) = o1;
                }
            }
            __syncthreads();

            // ---- Layer 2: [64k][128e] x W2b -> m2T [32][128] ----
            {
                const int cg = tid & 7, eg = tid >> 3;
                const int e0 = eg*4, c0 = cg*4;
                float acc[4][4];
                #pragma unroll
                for (int ei = 0; ei < 4; ++ei) {
                    acc[ei][0] = sb2b[c0]; acc[ei][1] = sb2b[c0+1];
                    acc[ei][2] = sb2b[c0+2]; acc[ei][3] = sb2b[c0+3];
                }
                #pragma unroll 4
                for (int k = 0; k < 64; ++k) {
                    float4 a = *(const float4*)(m1T + k*ST + e0);
                    float4 w = *(const float4*)(sW2b + k*32 + c0);
                    float av[4] = {a.x, a.y, a.z, a.w};
                    #pragma unroll
                    for (int ei = 0; ei < 4; ++ei) {
                        acc[ei][0] += av[ei]*w.x; acc[ei][1] += av[ei]*w.y;
                        acc[ei][2] += av[ei]*w.z; acc[ei][3] += av[ei]*w.w;
                    }
                }
                #pragma unroll
                for (int ci = 0; ci < 4; ++ci) {
                    float4 o = make_float4(gelu_f(acc[0][ci]), gelu_f(acc[1][ci]),
                                           gelu_f(acc[2][ci]), gelu_f(acc[3][ci]));
                    *(float4*)(m2T + (c0+ci)*ST + e0) = o;
                }
            }
            __syncthreads();

            // ---- Layer 3: [32k][128e] x W2c -> m3T [32][128] ----
            {
                const int cg = tid & 7, eg = tid >> 3;
                const int e0 = eg*4, c0 = cg*4;
                float acc[4][4];
                #pragma unroll
                for (int ei = 0; ei < 4; ++ei) {
                    acc[ei][0] = sb2c[c0]; acc[ei][1] = sb2c[c0+1];
                    acc[ei][2] = sb2c[c0+2]; acc[ei][3] = sb2c[c0+3];
                }
                #pragma unroll 4
                for (int k = 0; k < 32; ++k) {
                    float4 a = *(const float4*)(m2T + k*ST + e0);
                    float4 w = *(const float4*)(sW2c + k*32 + c0);
                    float av[4] = {a.x, a.y, a.z, a.w};
                    #pragma unroll
                    for (int ei = 0; ei < 4; ++ei) {
                        acc[ei][0] += av[ei]*w.x; acc[ei][1] += av[ei]*w.y;
                        acc[ei][2] += av[ei]*w.z; acc[ei][3] += av[ei]*w.w;
                    }
                }
                #pragma unroll
                for (int ci = 0; ci < 4; ++ci) {
                    float4 o = make_float4(gelu_f(acc[0][ci]), gelu_f(acc[1][ci]),
                                           gelu_f(acc[2][ci]), gelu_f(acc[3][ci]));
                    *(float4*)(m3T + (c0+ci)*ST + e0) = o;
                }
            }
            __syncthreads();

            // ---- segment-sum (this chunk) + build next chunk ----
            if (tid < 128) {
                const int n = tid >> 5, cc = tid & 31;
                const float* r = m3T + cc*ST + n*31;
                float s = 0.f;
                #pragma unroll
                for (int q = 0; q < 31; ++q) s += r[q];
                sMi[(c*4 + n)*35 + cc] = s;
            }
            if (c < 7)
                build_chunk(c+1, tid, b, edge_g, uT, sNT, sJs, sW2a, sb2a, sBase);
            __syncthreads();
        }

        // ---- GRU cell (GELU new gate) ----
        {
            const int n  = tid >> 3;
            const int c0 = (tid & 7) << 3;
            float ar[8], az[8], an_[8], hn_[8];
            #pragma unroll
            for (int o = 0; o < 8; ++o) {
                ar[o]  = p.bih[c0+o]      + p.bhh[c0+o];
                az[o]  = p.bih[64+c0+o]   + p.bhh[64+c0+o];
                an_[o] = p.bih[128+c0+o];
                hn_[o] = p.bhh[128+c0+o];
            }
            const float* mi = sMi + n*35;
            #pragma unroll 2
            for (int k = 0; k < 34; ++k) {
                float a = mi[k];
                const float* w = p.Wih + k*192;
                float4 r0 = *(const float4*)(w + c0);
                float4 r1 = *(const float4*)(w + c0 + 4);
                float4 z0 = *(const float4*)(w + 64 + c0);
                float4 z1 = *(const float4*)(w + 64 + c0 + 4);
                float4 n0 = *(const float4*)(w + 128 + c0);
                float4 n1 = *(const float4*)(w + 128 + c0 + 4);
                FMA8(ar, a, r0, r1); FMA8(az, a, z0, z1); FMA8(an_, a, n0, n1);
            }
            const float* hv = sH + n*65;
            #pragma unroll 2
            for (int k = 0; k < 64; ++k) {
                float a = hv[k];
                const float* w = p.Whh + k*192;
                float4 r0 = *(const float4*)(w + c0);
                float4 r1 = *(const float4*)(w + c0 + 4);
                float4 z0 = *(const float4*)(w + 64 + c0);
                float4 z1 = *(const float4*)(w + 64 + c0 + 4);
                float4 n0 = *(const float4*)(w + 128 + c0);
                float4 n1 = *(const float4*)(w + 128 + c0 + 4);
                FMA8(ar, a, r0, r1); FMA8(az, a, z0, z1); FMA8(hn_, a, n0, n1);
            }
            float hnew[8];
            #pragma unroll
            for (int o = 0; o < 8; ++o) {
                float r = sigm_f(ar[o]);
                float z = sigm_f(az[o]);
                float g = gelu_f(an_[o] + r * hn_[o]);
                hnew[o] = (1.0f - z) * g + z * hv[c0 + o];
            }
            __syncthreads();
            #pragma unroll
            for (int o = 0; o < 8; ++o) sH[n*65 + c0 + o] = hnew[o];
        }
        __syncthreads();

        // ---- node = h @ W3b + b3b  (write transposed into sNT) ----
        {
            const int n = tid >> 3, f0 = (tid & 7) << 2;
            float a0 = p.b3b[f0], a1 = p.b3b[f0+1], a2 = p.b3b[f0+2], a3 = p.b3b[f0+3];
            const float* hv = sH + n*65;
            #pragma unroll 8
            for (int k = 0; k < 64; ++k) {
                float a = hv[k];
                float4 w = *(const float4*)(p.W3b + k*32 + f0);
                a0 += a*w.x; a1 += a*w.y; a2 += a*w.z; a3 += a*w.w;
            }
            sNT[(f0+0)*33 + n] = a0; sNT[(f0+1)*33 + n] = a1;
            sNT[(f0+2)*33 + n] = a2; sNT[(f0+3)*33 + n] = a3;
        }
        __syncthreads();
    }

    // ---- readout ----
    {   // t1 = node @ W4a + b4a : [32][64] into bufA (stride 68)
        const int n = tid >> 3, f0 = (tid & 7) << 3;
        float acc[8];
        #pragma unroll
        for (int o = 0; o < 8; ++o) acc[o] = p.b4a[f0 + o];
        #pragma unroll 8
        for (int k = 0; k < 32; ++k) {
            float a = sNT[k*33 + n];
            float4 w0 = *(const float4*)(p.W4a + k*64 + f0);
            float4 w1 = *(const float4*)(p.W4a + k*64 + f0 + 4);
            FMA8(acc, a, w0, w1);
        }
        #pragma unroll
        for (int o = 0; o < 8; ++o) bufA[n*68 + f0 + o] = acc[o];
    }
    __syncthreads();
    {   // t2 = t1 @ W4b + b4b : [32][32] into bufB (stride 36)
        const int n = tid >> 3, f0 = (tid & 7) << 2;
        float a0 = p.b4b[f0], a1 = p.b4b[f0+1], a2 = p.b4b[f0+2], a3 = p.b4b[f0+3];
        const float* r = bufA + n*68;
        #pragma unroll 8
        for (int k = 0; k < 64; ++k) {
            float a = r[k];
            float4 w = *(const float4*)(p.W4b + k*32 + f0);
            a0 += a*w.x; a1 += a*w.y; a2 += a*w.z; a3 += a*w.w;
        }
        float* o = bufB + n*36 + f0;
        o[0]=a0; o[1]=a1; o[2]=a2; o[3]=a3;
    }
    __syncthreads();
    {   // t3 = t2 @ W4c + b4c : [32][32] into bufA (stride 36)
        const int n = tid >> 3, f0 = (tid & 7) << 2;
        float a0 = p.b4c[f0], a1 = p.b4c[f0+1], a2 = p.b4c[f0+2], a3 = p.b4c[f0+3];
        const float* r = bufB + n*36;
        #pragma unroll 8
        for (int k = 0; k < 32; ++k) {
            float a = r[k];
            float4 w = *(const float4*)(p.W4c + k*32 + f0);
            a0 += a*w.x; a1 += a*w.y; a2 += a*w.z; a3 += a*w.w;
        }
        float* o = bufA + n*36 + f0;
        o[0]=a0; o[1]=a1; o[2]=a2; o[3]=a3;
    }
    __syncthreads();
    {   // t4 = t3 @ W5a + b5a : [32][16] into bufB (stride 18)
        const int n = tid >> 3, f0 = (tid & 7) << 1;
        float a0 = p.b5a[f0], a1 = p.b5a[f0 + 1];
        const float* r = bufA + n*36;
        #pragma unroll 8
        for (int k = 0; k < 32; ++k) {
            float a = r[k];
            a0 += a * p.W5a[k*16 + f0];
            a1 += a * p.W5a[k*16 + f0 + 1];
        }
        bufB[n*18 + f0]     = a0;
        bufB[n*18 + f0 + 1] = a1;
    }
    __syncthreads();
    if (tid < 64) {
        const int n = tid >> 1, col = tid & 1;
        float acc = p.b5b[col];
        const float* r = bufB + n*18;
        #pragma unroll
        for (int k = 0; k < 16; ++k) acc += r[k] * p.W5b[k*2 + col];
        if (col == 0) p.out[b*32 + n] = acc;
        else          p.out[32768 + b*32 + n] = 1.0f / acc;
    }
}

extern "C" void kernel_launch(void* const* d_in, const int* in_sizes, int n_in,
                              void* d_out, int out_size) {
    const int has_iter = (n_in >= 32) ? 1 : 0;
    const int base = has_iter ? 8 : 7;

    GnnParams p;
    p.node0 = (const float*)d_in[0];
    p.edge  = (const float*)d_in[1];
    p.h0    = (const float*)d_in[2];
    p.mean  = (const float*)d_in[3];
    p.vari  = (const float*)d_in[4];
    p.ujs   = (const int*)d_in[6];
    p.iterp = has_iter ? (const int*)d_in[7] : nullptr;
    p.W1a = (const float*)d_in[base+0];  p.b1a = (const float*)d_in[base+1];
    p.W2a = (const float*)d_in[base+2];  p.b2a = (const float*)d_in[base+3];
    p.W2b = (const float*)d_in[base+4];  p.b2b = (const float*)d_in[base+5];
    p.W2c = (const float*)d_in[base+6];  p.b2c = (const float*)d_in[base+7];
    p.Wih = (const float*)d_in[base+8];  p.Whh = (const float*)d_in[base+9];
    p.bih = (const float*)d_in[base+10]; p.bhh = (const float*)d_in[base+11];
    p.W3b = (const float*)d_in[base+12]; p.b3b = (const float*)d_in[base+13];
    p.W4a = (const float*)d_in[base+14]; p.b4a = (const float*)d_in[base+15];
    p.W4b = (const float*)d_in[base+16]; p.b4b = (const float*)d_in[base+17];
    p.W4c = (const float*)d_in[base+18]; p.b4c = (const float*)d_in[base+19];
    p.W5a = (const float*)d_in[base+20]; p.b5a = (const float*)d_in[base+21];
    p.W5b = (const float*)d_in[base+22]; p.b5b = (const float*)d_in[base+23];
    p.out = (float*)d_out;

    cudaFuncSetAttribute(gnn_kernel,
                         cudaFuncAttributeMaxDynamicSharedMemorySize,
                         SMEM_FLOATS * (int)sizeof(float));
    gnn_kernel<<<1024, NT, SMEM_FLOATS * sizeof(float)>>>(p);
}

// round 3
// speedup vs baseline: 3.1442x; 1.2001x over previous
#include <cuda_runtime.h>
#include <math.h>

#define NT 256
#define ST 132   // edge-buffer row stride (128 slots + 4 pad)

// Shared layout (float offsets)
#define OFF_W45   0        // W2a rows 64,65 : 128
#define OFF_W2B   128      // [64][32] = 2048
#define OFF_B2B   2176     // 32
#define OFF_W2C   2208     // [32][32] = 1024
#define OFF_B2C   3232     // 32
#define OFF_NT    3264     // nodeT [32 feat][32 node] stride 33 = 1056
#define OFF_H     4320     // [32][65] = 2080
#define OFF_MI    6400     // [32][35] = 1120
#define OFF_JS    7520     // 992 ints
#define OFF_EDGE  8512     // [992][2] = 1984
#define OFF_BASE  10496    // [32][68] = 2176
#define OFF_PROJ  12672    // [32][68] = 2176
#define OFF_A     14848    // bufA: staged W2a[0:64]+b2a (4160) / m2T [32][132] = 4224
#define OFF_B     19072    // bufB: m1T [64][132] = 8448 / m3T [32][132]
#define SMEM_FLOATS 27520  // 110,080 B -> 2 CTAs/SM

__device__ __forceinline__ float gelu_f(float x) {
    return 0.5f * x * (1.0f + erff(x * 0.7071067811865476f));
}
__device__ __forceinline__ float sigm_f(float x) {
    return 1.0f / (1.0f + __expf(-x));
}

#define FMA8(acc, a, w0, w1) do { \
    acc[0] += (a) * (w0).x; acc[1] += (a) * (w0).y; \
    acc[2] += (a) * (w0).z; acc[3] += (a) * (w0).w; \
    acc[4] += (a) * (w1).x; acc[5] += (a) * (w1).y; \
    acc[6] += (a) * (w1).z; acc[7] += (a) * (w1).w; } while (0)

struct GnnParams {
    const float *node0, *edge, *h0, *mean, *vari;
    const int   *ujs, *iterp;
    const float *W1a, *b1a, *W2a, *b2a, *W2b, *b2b, *W2c, *b2c;
    const float *Wih, *Whh, *bih, *bhh, *W3b, *b3b;
    const float *W4a, *b4a, *W4b, *b4b, *W4c, *b4c, *W5a, *b5a, *W5b, *b5b;
    float *out;
};

__global__ __launch_bounds__(NT)
void gnn_kernel(GnnParams p) {
    extern __shared__ float sm[];
    const int tid = threadIdx.x;
    const int b   = blockIdx.x;

    float* sW45  = sm + OFF_W45;
    float* sW2b  = sm + OFF_W2B;
    float* sb2b  = sm + OFF_B2B;
    float* sW2c  = sm + OFF_W2C;
    float* sb2c  = sm + OFF_B2C;
    float* sNT   = sm + OFF_NT;    // node^T [feat][node], stride 33
    float* sH    = sm + OFF_H;     // stride 65
    float* sMi   = sm + OFF_MI;    // stride 35
    int*   sJs   = (int*)(sm + OFF_JS);
    float* sEdge = sm + OFF_EDGE;
    float* sBase = sm + OFF_BASE;  // stride 68
    float* sProj = sm + OFF_PROJ;  // stride 68
    float* bufA  = sm + OFF_A;
    float* bufB  = sm + OFF_B;

    // ---- init copies ----
    for (int i = tid; i < 128;   i += NT) sW45[i] = p.W2a[64*64 + i];
    for (int i = tid; i < 64*32; i += NT) sW2b[i] = p.W2b[i];
    for (int i = tid; i < 32;    i += NT) sb2b[i] = p.b2b[i];
    for (int i = tid; i < 32*32; i += NT) sW2c[i] = p.W2c[i];
    for (int i = tid; i < 32;    i += NT) sb2c[i] = p.b2c[i];
    for (int i = tid; i < 992;   i += NT) sJs[i]  = p.ujs[i];
    for (int i = tid; i < 992*2; i += NT) sEdge[i] = p.edge[b*1984 + i];
    for (int i = tid; i < 32*64; i += NT) {
        int n = i >> 6, k = i & 63;
        sH[n*65 + k] = p.h0[b*2048 + i];
    }
    for (int i = tid; i < 1024; i += NT) bufB[i] = p.node0[b*1024 + i];
    if (tid < 32) {
        sMi[tid*35 + 32] = p.mean[b*32 + tid];
        sMi[tid*35 + 33] = 1.0f / p.vari[b*32 + tid];
    }
    __syncthreads();

    // ---- node = node0 @ W1a + b1a (write transposed into sNT) ----
    {
        const int n = tid >> 3, f0 = (tid & 7) << 2;
        float a0 = p.b1a[f0], a1 = p.b1a[f0+1], a2 = p.b1a[f0+2], a3 = p.b1a[f0+3];
        const float* r = bufB + n*32;
        #pragma unroll 8
        for (int k = 0; k < 32; ++k) {
            float a = r[k];
            float4 w = *(const float4*)(p.W1a + k*32 + f0);
            a0 += a*w.x; a1 += a*w.y; a2 += a*w.z; a3 += a*w.w;
        }
        sNT[(f0+0)*33 + n] = a0; sNT[(f0+1)*33 + n] = a1;
        sNT[(f0+2)*33 + n] = a2; sNT[(f0+3)*33 + n] = a3;
    }
    __syncthreads();

    const int iters = p.iterp ? *p.iterp : 3;

    for (int it = 0; it < iters; ++it) {
        // ---- stage W2a rows 0..63 + b2a into bufA ----
        for (int i = tid; i < 4096; i += NT) bufA[i] = p.W2a[i];
        for (int i = tid + 4096; i < 4160; i += NT) bufA[i] = p.b2a[i - 4096];
        __syncthreads();

        // ---- base = node@W2a[0:32]+b2a ; proj = node@W2a[32:64] ----
        {
            const int n = tid >> 3, c0 = (tid & 7) << 3;
            float bacc[8], pacc[8];
            {
                float4 b0 = *(const float4*)(bufA + 4096 + c0);
                float4 b1 = *(const float4*)(bufA + 4096 + c0 + 4);
                bacc[0]=b0.x; bacc[1]=b0.y; bacc[2]=b0.z; bacc[3]=b0.w;
                bacc[4]=b1.x; bacc[5]=b1.y; bacc[6]=b1.z; bacc[7]=b1.w;
            }
            #pragma unroll
            for (int o = 0; o < 8; ++o) pacc[o] = 0.0f;
            #pragma unroll 4
            for (int k = 0; k < 32; ++k) {
                float a = sNT[k*33 + n];
                float4 wb0 = *(const float4*)(bufA + k*64 + c0);
                float4 wb1 = *(const float4*)(bufA + k*64 + c0 + 4);
                float4 wp0 = *(const float4*)(bufA + (32+k)*64 + c0);
                float4 wp1 = *(const float4*)(bufA + (32+k)*64 + c0 + 4);
                FMA8(bacc, a, wb0, wb1);
                FMA8(pacc, a, wp0, wp1);
            }
            #pragma unroll
            for (int o = 0; o < 8; o += 4) {
                *(float4*)(sBase + n*68 + c0 + o) =
                    make_float4(bacc[o], bacc[o+1], bacc[o+2], bacc[o+3]);
                *(float4*)(sProj + n*68 + c0 + o) =
                    make_float4(pacc[o], pacc[o+1], pacc[o+2], pacc[o+3]);
            }
        }
        __syncthreads();

        for (int c = 0; c < 8; ++c) {
            const int ce0 = c * 124;
            // ---- Layer 1 (rank-2 + gathers): m1T[64][128] ----
            {
                const int cg = tid & 15, eg = tid >> 4;
                const int e0 = eg*8, c0 = cg*4;
                const float4 w64 = *(const float4*)(sW45 + c0);
                const float4 w65 = *(const float4*)(sW45 + 64 + c0);
                float acc[8][4];
                #pragma unroll
                for (int ei = 0; ei < 8; ++ei) {
                    const int e = e0 + ei;
                    int n2 = (e * 2115) >> 16; if (n2 > 3) n2 = 3;
                    const bool valid = e < 124;
                    const int ge = ce0 + e;
                    const int j  = valid ? sJs[ge] : 0;
                    float ev0 = 0.f, ev1 = 0.f;
                    if (valid) { ev0 = sEdge[ge*2]; ev1 = sEdge[ge*2+1]; }
                    const float4 bs = *(const float4*)(sBase + (c*4 + n2)*68 + c0);
                    const float4 pr = *(const float4*)(sProj + j*68 + c0);
                    acc[ei][0] = bs.x + pr.x + ev0*w64.x + ev1*w65.x;
                    acc[ei][1] = bs.y + pr.y + ev0*w64.y + ev1*w65.y;
                    acc[ei][2] = bs.z + pr.z + ev0*w64.z + ev1*w65.z;
                    acc[ei][3] = bs.w + pr.w + ev0*w64.w + ev1*w65.w;
                }
                #pragma unroll
                for (int ci = 0; ci < 4; ++ci) {
                    float4 o0 = make_float4(gelu_f(acc[0][ci]), gelu_f(acc[1][ci]),
                                            gelu_f(acc[2][ci]), gelu_f(acc[3][ci]));
                    float4 o1 = make_float4(gelu_f(acc[4][ci]), gelu_f(acc[5][ci]),
                                            gelu_f(acc[6][ci]), gelu_f(acc[7][ci]));
                    *(float4*)(bufB + (c0+ci)*ST + e0)     = o0;
                    *(float4*)(bufB + (c0+ci)*ST + e0 + 4) = o1;
                }
            }
            __syncthreads();

            // ---- Layer 2: [64k][128e] x W2b -> m2T (bufA) ----
            {
                const int cg = tid & 7, eg = tid >> 3;
                const int e0 = eg*4, c0 = cg*4;
                float acc[4][4];
                #pragma unroll
                for (int ei = 0; ei < 4; ++ei) {
                    acc[ei][0] = sb2b[c0]; acc[ei][1] = sb2b[c0+1];
                    acc[ei][2] = sb2b[c0+2]; acc[ei][3] = sb2b[c0+3];
                }
                #pragma unroll 4
                for (int k = 0; k < 64; ++k) {
                    float4 a = *(const float4*)(bufB + k*ST + e0);
                    float4 w = *(const float4*)(sW2b + k*32 + c0);
                    float av[4] = {a.x, a.y, a.z, a.w};
                    #pragma unroll
                    for (int ei = 0; ei < 4; ++ei) {
                        acc[ei][0] += av[ei]*w.x; acc[ei][1] += av[ei]*w.y;
                        acc[ei][2] += av[ei]*w.z; acc[ei][3] += av[ei]*w.w;
                    }
                }
                #pragma unroll
                for (int ci = 0; ci < 4; ++ci) {
                    *(float4*)(bufA + (c0+ci)*ST + e0) =
                        make_float4(gelu_f(acc[0][ci]), gelu_f(acc[1][ci]),
                                    gelu_f(acc[2][ci]), gelu_f(acc[3][ci]));
                }
            }
            __syncthreads();

            // ---- Layer 3: [32k][128e] x W2c -> m3T (bufB) ----
            {
                const int cg = tid & 7, eg = tid >> 3;
                const int e0 = eg*4, c0 = cg*4;
                float acc[4][4];
                #pragma unroll
                for (int ei = 0; ei < 4; ++ei) {
                    acc[ei][0] = sb2c[c0]; acc[ei][1] = sb2c[c0+1];
                    acc[ei][2] = sb2c[c0+2]; acc[ei][3] = sb2c[c0+3];
                }
                #pragma unroll 4
                for (int k = 0; k < 32; ++k) {
                    float4 a = *(const float4*)(bufA + k*ST + e0);
                    float4 w = *(const float4*)(sW2c + k*32 + c0);
                    float av[4] = {a.x, a.y, a.z, a.w};
                    #pragma unroll
                    for (int ei = 0; ei < 4; ++ei) {
                        acc[ei][0] += av[ei]*w.x; acc[ei][1] += av[ei]*w.y;
                        acc[ei][2] += av[ei]*w.z; acc[ei][3] += av[ei]*w.w;
                    }
                }
                #pragma unroll
                for (int ci = 0; ci < 4; ++ci) {
                    *(float4*)(bufB + (c0+ci)*ST + e0) =
                        make_float4(gelu_f(acc[0][ci]), gelu_f(acc[1][ci]),
                                    gelu_f(acc[2][ci]), gelu_f(acc[3][ci]));
                }
            }
            __syncthreads();

            // ---- segment-sum over 31 edges per node ----
            if (tid < 128) {
                const int n = tid >> 5, cc = tid & 31;
                const float* r = bufB + cc*ST + n*31;
                float s = 0.f;
                #pragma unroll
                for (int q = 0; q < 31; ++q) s += r[q];
                sMi[(c*4 + n)*35 + cc] = s;
            }
            __syncthreads();
        }

        // ---- GRU cell (GELU new gate) ----
        {
            const int n  = tid >> 3;
            const int c0 = (tid & 7) << 3;
            float ar[8], az[8], an_[8], hn_[8];
            #pragma unroll
            for (int o = 0; o < 8; ++o) {
                ar[o]  = p.bih[c0+o]      + p.bhh[c0+o];
                az[o]  = p.bih[64+c0+o]   + p.bhh[64+c0+o];
                an_[o] = p.bih[128+c0+o];
                hn_[o] = p.bhh[128+c0+o];
            }
            const float* mi = sMi + n*35;
            #pragma unroll 2
            for (int k = 0; k < 34; ++k) {
                float a = mi[k];
                const float* w = p.Wih + k*192;
                float4 r0 = *(const float4*)(w + c0);
                float4 r1 = *(const float4*)(w + c0 + 4);
                float4 z0 = *(const float4*)(w + 64 + c0);
                float4 z1 = *(const float4*)(w + 64 + c0 + 4);
                float4 n0 = *(const float4*)(w + 128 + c0);
                float4 n1 = *(const float4*)(w + 128 + c0 + 4);
                FMA8(ar, a, r0, r1); FMA8(az, a, z0, z1); FMA8(an_, a, n0, n1);
            }
            const float* hv = sH + n*65;
            #pragma unroll 2
            for (int k = 0; k < 64; ++k) {
                float a = hv[k];
                const float* w = p.Whh + k*192;
                float4 r0 = *(const float4*)(w + c0);
                float4 r1 = *(const float4*)(w + c0 + 4);
                float4 z0 = *(const float4*)(w + 64 + c0);
                float4 z1 = *(const float4*)(w + 64 + c0 + 4);
                float4 n0 = *(const float4*)(w + 128 + c0);
                float4 n1 = *(const float4*)(w + 128 + c0 + 4);
                FMA8(ar, a, r0, r1); FMA8(az, a, z0, z1); FMA8(hn_, a, n0, n1);
            }
            float hnew[8];
            #pragma unroll
            for (int o = 0; o < 8; ++o) {
                float r = sigm_f(ar[o]);
                float z = sigm_f(az[o]);
                float g = gelu_f(an_[o] + r * hn_[o]);
                hnew[o] = (1.0f - z) * g + z * hv[c0 + o];
            }
            __syncthreads();
            #pragma unroll
            for (int o = 0; o < 8; ++o) sH[n*65 + c0 + o] = hnew[o];
        }
        __syncthreads();

        // ---- node = h @ W3b + b3b  (write transposed into sNT) ----
        {
            const int n = tid >> 3, f0 = (tid & 7) << 2;
            float a0 = p.b3b[f0], a1 = p.b3b[f0+1], a2 = p.b3b[f0+2], a3 = p.b3b[f0+3];
            const float* hv = sH + n*65;
            #pragma unroll 8
            for (int k = 0; k < 64; ++k) {
                float a = hv[k];
                float4 w = *(const float4*)(p.W3b + k*32 + f0);
                a0 += a*w.x; a1 += a*w.y; a2 += a*w.z; a3 += a*w.w;
            }
            sNT[(f0+0)*33 + n] = a0; sNT[(f0+1)*33 + n] = a1;
            sNT[(f0+2)*33 + n] = a2; sNT[(f0+3)*33 + n] = a3;
        }
        __syncthreads();
    }

    // ---- readout ----
    {   // t1 = node @ W4a + b4a : [32][64] into bufA (stride 68)
        const int n = tid >> 3, f0 = (tid & 7) << 3;
        float acc[8];
        #pragma unroll
        for (int o = 0; o < 8; ++o) acc[o] = p.b4a[f0 + o];
        #pragma unroll 8
        for (int k = 0; k < 32; ++k) {
            float a = sNT[k*33 + n];
            float4 w0 = *(const float4*)(p.W4a + k*64 + f0);
            float4 w1 = *(const float4*)(p.W4a + k*64 + f0 + 4);
            FMA8(acc, a, w0, w1);
        }
        #pragma unroll
        for (int o = 0; o < 8; ++o) bufA[n*68 + f0 + o] = acc[o];
    }
    __syncthreads();
    {   // t2 = t1 @ W4b + b4b : [32][32] into bufB (stride 36)
        const int n = tid >> 3, f0 = (tid & 7) << 2;
        float a0 = p.b4b[f0], a1 = p.b4b[f0+1], a2 = p.b4b[f0+2], a3 = p.b4b[f0+3];
        const float* r = bufA + n*68;
        #pragma unroll 8
        for (int k = 0; k < 64; ++k) {
            float a = r[k];
            float4 w = *(const float4*)(p.W4b + k*32 + f0);
            a0 += a*w.x; a1 += a*w.y; a2 += a*w.z; a3 += a*w.w;
        }
        float* o = bufB + n*36 + f0;
        o[0]=a0; o[1]=a1; o[2]=a2; o[3]=a3;
    }
    __syncthreads();
    {   // t3 = t2 @ W4c + b4c : [32][32] into bufA (stride 36)
        const int n = tid >> 3, f0 = (tid & 7) << 2;
        float a0 = p.b4c[f0], a1 = p.b4c[f0+1], a2 = p.b4c[f0+2], a3 = p.b4c[f0+3];
        const float* r = bufB + n*36;
        #pragma unroll 8
        for (int k = 0; k < 32; ++k) {
            float a = r[k];
            float4 w = *(const float4*)(p.W4c + k*32 + f0);
            a0 += a*w.x; a1 += a*w.y; a2 += a*w.z; a3 += a*w.w;
        }
        float* o = bufA + n*36 + f0;
        o[0]=a0; o[1]=a1; o[2]=a2; o[3]=a3;
    }
    __syncthreads();
    {   // t4 = t3 @ W5a + b5a : [32][16] into bufB (stride 18)
        const int n = tid >> 3, f0 = (tid & 7) << 1;
        float a0 = p.b5a[f0], a1 = p.b5a[f0 + 1];
        const float* r = bufA + n*36;
        #pragma unroll 8
        for (int k = 0; k < 32; ++k) {
            float a = r[k];
            a0 += a * p.W5a[k*16 + f0];
            a1 += a * p.W5a[k*16 + f0 + 1];
        }
        bufB[n*18 + f0]     = a0;
        bufB[n*18 + f0 + 1] = a1;
    }
    __syncthreads();
    if (tid < 64) {
        const int n = tid >> 1, col = tid & 1;
        float acc = p.b5b[col];
        const float* r = bufB + n*18;
        #pragma unroll
        for (int k = 0; k < 16; ++k) acc += r[k] * p.W5b[k*2 + col];
        if (col == 0) p.out[b*32 + n] = acc;
        else          p.out[32768 + b*32 + n] = 1.0f / acc;
    }
}

extern "C" void kernel_launch(void* const* d_in, const int* in_sizes, int n_in,
                              void* d_out, int out_size) {
    const int has_iter = (n_in >= 32) ? 1 : 0;
    const int base = has_iter ? 8 : 7;

    GnnParams p;
    p.node0 = (const float*)d_in[0];
    p.edge  = (const float*)d_in[1];
    p.h0    = (const float*)d_in[2];
    p.mean  = (const float*)d_in[3];
    p.vari  = (const float*)d_in[4];
    p.ujs   = (const int*)d_in[6];
    p.iterp = has_iter ? (const int*)d_in[7] : nullptr;
    p.W1a = (const float*)d_in[base+0];  p.b1a = (const float*)d_in[base+1];
    p.W2a = (const float*)d_in[base+2];  p.b2a = (const float*)d_in[base+3];
    p.W2b = (const float*)d_in[base+4];  p.b2b = (const float*)d_in[base+5];
    p.W2c = (const float*)d_in[base+6];  p.b2c = (const float*)d_in[base+7];
    p.Wih = (const float*)d_in[base+8];  p.Whh = (const float*)d_in[base+9];
    p.bih = (const float*)d_in[base+10]; p.bhh = (const float*)d_in[base+11];
    p.W3b = (const float*)d_in[base+12]; p.b3b = (const float*)d_in[base+13];
    p.W4a = (const float*)d_in[base+14]; p.b4a = (const float*)d_in[base+15];
    p.W4b = (const float*)d_in[base+16]; p.b4b = (const float*)d_in[base+17];
    p.W4c = (const float*)d_in[base+18]; p.b4c = (const float*)d_in[base+19];
    p.W5a = (const float*)d_in[base+20]; p.b5a = (const float*)d_in[base+21];
    p.W5b = (const float*)d_in[base+22]; p.b5b = (const float*)d_in[base+23];
    p.out = (float*)d_out;

    cudaFuncSetAttribute(gnn_kernel,
                         cudaFuncAttributeMaxDynamicSharedMemorySize,
                         SMEM_FLOATS * (int)sizeof(float));
    gnn_kernel<<<1024, NT, SMEM_FLOATS * sizeof(float)>>>(p);
}

// round 4
// speedup vs baseline: 3.1533x; 1.0029x over previous
#include <cuda_runtime.h>
#include <math.h>

#define NT 256
#define ST 132   // edge-buffer row stride (128 slots + 4 pad)

typedef unsigned long long ull;

// Shared layout (float offsets)
#define OFF_W45   0        // W2a rows 64,65 : 128
#define OFF_W2B   128      // [64][32] = 2048
#define OFF_B2B   2176     // 32
#define OFF_W2C   2208     // [32][32] = 1024
#define OFF_B2C   3232     // 32
#define OFF_NT    3264     // nodeT [32 feat][32 node] stride 33 = 1056
#define OFF_H     4320     // [32][65] = 2080
#define OFF_MI    6400     // [32][35] = 1120
#define OFF_EDGE  7520     // [992][2] = 1984
#define OFF_BASE  9504     // [32][68] = 2176
#define OFF_PROJ  11680    // [32][68] = 2176
#define OFF_A     13856    // bufA: staged W2a[0:64]+b2a (4160) / m2T [32][132] = 4224
#define OFF_B     18080    // bufB: m1T [64][132] = 8448 / m3T [32][132]
#define SMEM_FLOATS 26528  // 106,112 B -> 2 CTAs/SM

__device__ __forceinline__ float gelu_f(float x) {
    return 0.5f * x * (1.0f + erff(x * 0.7071067811865476f));
}
__device__ __forceinline__ float sigm_f(float x) {
    return 1.0f / (1.0f + __expf(-x));
}

__device__ __forceinline__ ull pack2(float lo, float hi) {
    ull r; asm("mov.b64 %0, {%1, %2};" : "=l"(r) : "f"(lo), "f"(hi)); return r;
}
__device__ __forceinline__ ull dup2(float x) { return pack2(x, x); }
__device__ __forceinline__ void unpack2(ull v, float& lo, float& hi) {
    asm("mov.b64 {%0, %1}, %2;" : "=f"(lo), "=f"(hi) : "l"(v));
}
__device__ __forceinline__ ull fma2(ull a, ull b, ull c) {
    ull d; asm("fma.rn.f32x2 %0, %1, %2, %3;" : "=l"(d) : "l"(a), "l"(b), "l"(c));
    return d;
}
__device__ __forceinline__ ull add2(ull a, ull b) {
    ull d; asm("add.rn.f32x2 %0, %1, %2;" : "=l"(d) : "l"(a), "l"(b));
    return d;
}

struct GnnParams {
    const float *node0, *edge, *h0, *mean, *vari;
    const int   *iterp;
    const float *W1a, *b1a, *W2a, *b2a, *W2b, *b2b, *W2c, *b2c;
    const float *Wih, *Whh, *bih, *bhh, *W3b, *b3b;
    const float *W4a, *b4a, *W4b, *b4b, *W4c, *b4c, *W5a, *b5a, *W5b, *b5b;
    float *out;
};

__global__ __launch_bounds__(NT)
void gnn_kernel(GnnParams p) {
    extern __shared__ float sm[];
    const int tid = threadIdx.x;
    const int b   = blockIdx.x;

    float* sW45  = sm + OFF_W45;
    float* sW2b  = sm + OFF_W2B;
    float* sb2b  = sm + OFF_B2B;
    float* sW2c  = sm + OFF_W2C;
    float* sb2c  = sm + OFF_B2C;
    float* sNT   = sm + OFF_NT;    // node^T [feat][node], stride 33
    float* sH    = sm + OFF_H;     // stride 65
    float* sMi   = sm + OFF_MI;    // stride 35
    float* sEdge = sm + OFF_EDGE;
    float* sBase = sm + OFF_BASE;  // stride 68
    float* sProj = sm + OFF_PROJ;  // stride 68
    float* bufA  = sm + OFF_A;
    float* bufB  = sm + OFF_B;

    // ---- init copies ----
    for (int i = tid; i < 128;   i += NT) sW45[i] = p.W2a[64*64 + i];
    for (int i = tid; i < 64*32; i += NT) sW2b[i] = p.W2b[i];
    for (int i = tid; i < 32;    i += NT) sb2b[i] = p.b2b[i];
    for (int i = tid; i < 32*32; i += NT) sW2c[i] = p.W2c[i];
    for (int i = tid; i < 32;    i += NT) sb2c[i] = p.b2c[i];
    for (int i = tid; i < 992*2; i += NT) sEdge[i] = p.edge[b*1984 + i];
    for (int i = tid; i < 32*64; i += NT) {
        int n = i >> 6, k = i & 63;
        sH[n*65 + k] = p.h0[b*2048 + i];
    }
    for (int i = tid; i < 1024; i += NT) bufB[i] = p.node0[b*1024 + i];
    if (tid < 32) {
        sMi[tid*35 + 32] = p.mean[b*32 + tid];
        sMi[tid*35 + 33] = 1.0f / p.vari[b*32 + tid];
    }
    __syncthreads();

    // ---- node = node0 @ W1a + b1a (write transposed into sNT) ----
    {
        const int n = tid >> 3, f0 = (tid & 7) << 2;
        float a0 = p.b1a[f0], a1 = p.b1a[f0+1], a2 = p.b1a[f0+2], a3 = p.b1a[f0+3];
        const float* r = bufB + n*32;
        #pragma unroll 8
        for (int k = 0; k < 32; ++k) {
            float a = r[k];
            float4 w = *(const float4*)(p.W1a + k*32 + f0);
            a0 += a*w.x; a1 += a*w.y; a2 += a*w.z; a3 += a*w.w;
        }
        sNT[(f0+0)*33 + n] = a0; sNT[(f0+1)*33 + n] = a1;
        sNT[(f0+2)*33 + n] = a2; sNT[(f0+3)*33 + n] = a3;
    }
    __syncthreads();

    const int iters = p.iterp ? *p.iterp : 3;

    for (int it = 0; it < iters; ++it) {
        // ---- stage W2a rows 0..63 + b2a into bufA ----
        for (int i = tid; i < 4096; i += NT) bufA[i] = p.W2a[i];
        for (int i = tid + 4096; i < 4160; i += NT) bufA[i] = p.b2a[i - 4096];
        __syncthreads();

        // ---- base = node@W2a[0:32]+b2a ; proj = node@W2a[32:64] (packed) ----
        {
            const int n = tid >> 3, c0 = (tid & 7) << 3;
            ull bacc[4], pacc[4];
            {
                ulonglong2 b0 = *(const ulonglong2*)(bufA + 4096 + c0);
                ulonglong2 b1 = *(const ulonglong2*)(bufA + 4096 + c0 + 4);
                bacc[0]=b0.x; bacc[1]=b0.y; bacc[2]=b1.x; bacc[3]=b1.y;
            }
            const ull z = dup2(0.0f);
            #pragma unroll
            for (int o = 0; o < 4; ++o) pacc[o] = z;
            #pragma unroll 4
            for (int k = 0; k < 32; ++k) {
                ull aa = dup2(sNT[k*33 + n]);
                ulonglong2 wb0 = *(const ulonglong2*)(bufA + k*64 + c0);
                ulonglong2 wb1 = *(const ulonglong2*)(bufA + k*64 + c0 + 4);
                ulonglong2 wp0 = *(const ulonglong2*)(bufA + (32+k)*64 + c0);
                ulonglong2 wp1 = *(const ulonglong2*)(bufA + (32+k)*64 + c0 + 4);
                bacc[0] = fma2(aa, wb0.x, bacc[0]); bacc[1] = fma2(aa, wb0.y, bacc[1]);
                bacc[2] = fma2(aa, wb1.x, bacc[2]); bacc[3] = fma2(aa, wb1.y, bacc[3]);
                pacc[0] = fma2(aa, wp0.x, pacc[0]); pacc[1] = fma2(aa, wp0.y, pacc[1]);
                pacc[2] = fma2(aa, wp1.x, pacc[2]); pacc[3] = fma2(aa, wp1.y, pacc[3]);
            }
            *(ulonglong2*)(sBase + n*68 + c0)     = make_ulonglong2(bacc[0], bacc[1]);
            *(ulonglong2*)(sBase + n*68 + c0 + 4) = make_ulonglong2(bacc[2], bacc[3]);
            *(ulonglong2*)(sProj + n*68 + c0)     = make_ulonglong2(pacc[0], pacc[1]);
            *(ulonglong2*)(sProj + n*68 + c0 + 4) = make_ulonglong2(pacc[2], pacc[3]);
        }
        __syncthreads();

        for (int c = 0; c < 8; ++c) {
            const int ce0 = c * 124;
            // ---- Layer 1 (rank-2, packed col-pairs): m1T[64][128] ----
            {
                const int cg = tid & 15, eg = tid >> 4;
                const int e0 = eg*8, c0 = cg*4;
                const ulonglong2 w64 = *(const ulonglong2*)(sW45 + c0);
                const ulonglong2 w65 = *(const ulonglong2*)(sW45 + 64 + c0);
                float acc[8][4];
                #pragma unroll
                for (int ei = 0; ei < 8; ++ei) {
                    const int e = e0 + ei;
                    int n2 = (e * 2115) >> 16; if (n2 > 3) n2 = 3;
                    const int i_glob = c*4 + n2;
                    const int q = e - n2*31;
                    int j = (q + (q >= i_glob)) & 31;
                    const bool valid = e < 124;
                    const int ge = ce0 + e;
                    float ev0 = 0.f, ev1 = 0.f;
                    if (valid) { ev0 = sEdge[ge*2]; ev1 = sEdge[ge*2+1]; }
                    ulonglong2 bs = *(const ulonglong2*)(sBase + i_glob*68 + c0);
                    ulonglong2 pr = *(const ulonglong2*)(sProj + j*68 + c0);
                    ull e0d = dup2(ev0), e1d = dup2(ev1);
                    ull s0 = add2(bs.x, pr.x);
                    ull s1 = add2(bs.y, pr.y);
                    s0 = fma2(e0d, w64.x, s0); s1 = fma2(e0d, w64.y, s1);
                    s0 = fma2(e1d, w65.x, s0); s1 = fma2(e1d, w65.y, s1);
                    unpack2(s0, acc[ei][0], acc[ei][1]);
                    unpack2(s1, acc[ei][2], acc[ei][3]);
                }
                #pragma unroll
                for (int ci = 0; ci < 4; ++ci) {
                    float4 o0 = make_float4(gelu_f(acc[0][ci]), gelu_f(acc[1][ci]),
                                            gelu_f(acc[2][ci]), gelu_f(acc[3][ci]));
                    float4 o1 = make_float4(gelu_f(acc[4][ci]), gelu_f(acc[5][ci]),
                                            gelu_f(acc[6][ci]), gelu_f(acc[7][ci]));
                    *(float4*)(bufB + (c0+ci)*ST + e0)     = o0;
                    *(float4*)(bufB + (c0+ci)*ST + e0 + 4) = o1;
                }
            }
            __syncthreads();

            // ---- Layer 2: [64k][128e] x W2b -> m2T (bufA), edge-pair packed ----
            {
                const int cg = tid & 7, eg = tid >> 3;
                const int e0 = eg*4, c0 = cg*4;
                ull acc[2][4];
                #pragma unroll
                for (int ci = 0; ci < 4; ++ci) {
                    ull bb = dup2(sb2b[c0+ci]);
                    acc[0][ci] = bb; acc[1][ci] = bb;
                }
                #pragma unroll 4
                for (int k = 0; k < 64; ++k) {
                    ulonglong2 a2 = *(const ulonglong2*)(bufB + k*ST + e0);
                    float4 w = *(const float4*)(sW2b + k*32 + c0);
                    ull w0 = dup2(w.x), w1 = dup2(w.y), w2 = dup2(w.z), w3 = dup2(w.w);
                    acc[0][0] = fma2(a2.x, w0, acc[0][0]); acc[1][0] = fma2(a2.y, w0, acc[1][0]);
                    acc[0][1] = fma2(a2.x, w1, acc[0][1]); acc[1][1] = fma2(a2.y, w1, acc[1][1]);
                    acc[0][2] = fma2(a2.x, w2, acc[0][2]); acc[1][2] = fma2(a2.y, w2, acc[1][2]);
                    acc[0][3] = fma2(a2.x, w3, acc[0][3]); acc[1][3] = fma2(a2.y, w3, acc[1][3]);
                }
                #pragma unroll
                for (int ci = 0; ci < 4; ++ci) {
                    float v0, v1, v2, v3;
                    unpack2(acc[0][ci], v0, v1);
                    unpack2(acc[1][ci], v2, v3);
                    *(float4*)(bufA + (c0+ci)*ST + e0) =
                        make_float4(gelu_f(v0), gelu_f(v1), gelu_f(v2), gelu_f(v3));
                }
            }
            __syncthreads();

            // ---- Layer 3: [32k][128e] x W2c -> m3T (bufB), edge-pair packed ----
            {
                const int cg = tid & 7, eg = tid >> 3;
                const int e0 = eg*4, c0 = cg*4;
                ull acc[2][4];
                #pragma unroll
                for (int ci = 0; ci < 4; ++ci) {
                    ull bb = dup2(sb2c[c0+ci]);
                    acc[0][ci] = bb; acc[1][ci] = bb;
                }
                #pragma unroll 4
                for (int k = 0; k < 32; ++k) {
                    ulonglong2 a2 = *(const ulonglong2*)(bufA + k*ST + e0);
                    float4 w = *(const float4*)(sW2c + k*32 + c0);
                    ull w0 = dup2(w.x), w1 = dup2(w.y), w2 = dup2(w.z), w3 = dup2(w.w);
                    acc[0][0] = fma2(a2.x, w0, acc[0][0]); acc[1][0] = fma2(a2.y, w0, acc[1][0]);
                    acc[0][1] = fma2(a2.x, w1, acc[0][1]); acc[1][1] = fma2(a2.y, w1, acc[1][1]);
                    acc[0][2] = fma2(a2.x, w2, acc[0][2]); acc[1][2] = fma2(a2.y, w2, acc[1][2]);
                    acc[0][3] = fma2(a2.x, w3, acc[0][3]); acc[1][3] = fma2(a2.y, w3, acc[1][3]);
                }
                #pragma unroll
                for (int ci = 0; ci < 4; ++ci) {
                    float v0, v1, v2, v3;
                    unpack2(acc[0][ci], v0, v1);
                    unpack2(acc[1][ci], v2, v3);
                    *(float4*)(bufB + (c0+ci)*ST + e0) =
                        make_float4(gelu_f(v0), gelu_f(v1), gelu_f(v2), gelu_f(v3));
                }
            }
            __syncthreads();

            // ---- segment-sum over 31 edges per node ----
            if (tid < 128) {
                const int n = tid >> 5, cc = tid & 31;
                const float* r = bufB + cc*ST + n*31;
                float s = 0.f;
                #pragma unroll
                for (int q = 0; q < 31; ++q) s += r[q];
                sMi[(c*4 + n)*35 + cc] = s;
            }
            __syncthreads();
        }

        // ---- GRU cell (GELU new gate), packed col-pairs ----
        {
            const int n  = tid >> 3;
            const int c0 = (tid & 7) << 3;
            ull ar[4], az[4], an_[4], hn_[4];
            #pragma unroll
            for (int o = 0; o < 4; ++o) {
                ull bi_r = *(const ull*)(p.bih + c0 + 2*o);
                ull bh_r = *(const ull*)(p.bhh + c0 + 2*o);
                ull bi_z = *(const ull*)(p.bih + 64 + c0 + 2*o);
                ull bh_z = *(const ull*)(p.bhh + 64 + c0 + 2*o);
                ar[o]  = add2(bi_r, bh_r);
                az[o]  = add2(bi_z, bh_z);
                an_[o] = *(const ull*)(p.bih + 128 + c0 + 2*o);
                hn_[o] = *(const ull*)(p.bhh + 128 + c0 + 2*o);
            }
            const float* mi = sMi + n*35;
            #pragma unroll 2
            for (int k = 0; k < 34; ++k) {
                ull aa = dup2(mi[k]);
                const float* w = p.Wih + k*192;
                ulonglong2 r01 = *(const ulonglong2*)(w + c0);
                ulonglong2 r23 = *(const ulonglong2*)(w + c0 + 4);
                ulonglong2 z01 = *(const ulonglong2*)(w + 64 + c0);
                ulonglong2 z23 = *(const ulonglong2*)(w + 64 + c0 + 4);
                ulonglong2 n01 = *(const ulonglong2*)(w + 128 + c0);
                ulonglong2 n23 = *(const ulonglong2*)(w + 128 + c0 + 4);
                ar[0]=fma2(aa,r01.x,ar[0]); ar[1]=fma2(aa,r01.y,ar[1]);
                ar[2]=fma2(aa,r23.x,ar[2]); ar[3]=fma2(aa,r23.y,ar[3]);
                az[0]=fma2(aa,z01.x,az[0]); az[1]=fma2(aa,z01.y,az[1]);
                az[2]=fma2(aa,z23.x,az[2]); az[3]=fma2(aa,z23.y,az[3]);
                an_[0]=fma2(aa,n01.x,an_[0]); an_[1]=fma2(aa,n01.y,an_[1]);
                an_[2]=fma2(aa,n23.x,an_[2]); an_[3]=fma2(aa,n23.y,an_[3]);
            }
            const float* hv = sH + n*65;
            #pragma unroll 2
            for (int k = 0; k < 64; ++k) {
                ull aa = dup2(hv[k]);
                const float* w = p.Whh + k*192;
                ulonglong2 r01 = *(const ulonglong2*)(w + c0);
                ulonglong2 r23 = *(const ulonglong2*)(w + c0 + 4);
                ulonglong2 z01 = *(const ulonglong2*)(w + 64 + c0);
                ulonglong2 z23 = *(const ulonglong2*)(w + 64 + c0 + 4);
                ulonglong2 n01 = *(const ulonglong2*)(w + 128 + c0);
                ulonglong2 n23 = *(const ulonglong2*)(w + 128 + c0 + 4);
                ar[0]=fma2(aa,r01.x,ar[0]); ar[1]=fma2(aa,r01.y,ar[1]);
                ar[2]=fma2(aa,r23.x,ar[2]); ar[3]=fma2(aa,r23.y,ar[3]);
                az[0]=fma2(aa,z01.x,az[0]); az[1]=fma2(aa,z01.y,az[1]);
                az[2]=fma2(aa,z23.x,az[2]); az[3]=fma2(aa,z23.y,az[3]);
                hn_[0]=fma2(aa,n01.x,hn_[0]); hn_[1]=fma2(aa,n01.y,hn_[1]);
                hn_[2]=fma2(aa,n23.x,hn_[2]); hn_[3]=fma2(aa,n23.y,hn_[3]);
            }
            float hnew[8];
            #pragma unroll
            for (int o = 0; o < 4; ++o) {
                float r0, r1, z0, z1, in0, in1, hn0, hn1;
                unpack2(ar[o], r0, r1);
                unpack2(az[o], z0, z1);
                unpack2(an_[o], in0, in1);
                unpack2(hn_[o], hn0, hn1);
                float rr0 = sigm_f(r0), rr1 = sigm_f(r1);
                float zz0 = sigm_f(z0), zz1 = sigm_f(z1);
                float g0 = gelu_f(in0 + rr0 * hn0);
                float g1 = gelu_f(in1 + rr1 * hn1);
                hnew[2*o]   = (1.0f - zz0) * g0 + zz0 * hv[c0 + 2*o];
                hnew[2*o+1] = (1.0f - zz1) * g1 + zz1 * hv[c0 + 2*o + 1];
            }
            __syncthreads();
            #pragma unroll
            for (int o = 0; o < 8; ++o) sH[n*65 + c0 + o] = hnew[o];
        }
        __syncthreads();

        // ---- node = h @ W3b + b3b  (packed, write transposed into sNT) ----
        {
            const int n = tid >> 3, f0 = (tid & 7) << 2;
            ull a01 = *(const ull*)(p.b3b + f0);
            ull a23 = *(const ull*)(p.b3b + f0 + 2);
            const float* hv = sH + n*65;
            #pragma unroll 4
            for (int k = 0; k < 64; ++k) {
                ull aa = dup2(hv[k]);
                ulonglong2 w2 = *(const ulonglong2*)(p.W3b + k*32 + f0);
                a01 = fma2(aa, w2.x, a01);
                a23 = fma2(aa, w2.y, a23);
            }
            float v0, v1, v2, v3;
            unpack2(a01, v0, v1); unpack2(a23, v2, v3);
            sNT[(f0+0)*33 + n] = v0; sNT[(f0+1)*33 + n] = v1;
            sNT[(f0+2)*33 + n] = v2; sNT[(f0+3)*33 + n] = v3;
        }
        __syncthreads();
    }

    // ---- readout ----
    {   // t1 = node @ W4a + b4a : [32][64] into bufA (stride 68), packed
        const int n = tid >> 3, f0 = (tid & 7) << 3;
        ull acc[4];
        acc[0] = *(const ull*)(p.b4a + f0);
        acc[1] = *(const ull*)(p.b4a + f0 + 2);
        acc[2] = *(const ull*)(p.b4a + f0 + 4);
        acc[3] = *(const ull*)(p.b4a + f0 + 6);
        #pragma unroll 4
        for (int k = 0; k < 32; ++k) {
            ull aa = dup2(sNT[k*33 + n]);
            ulonglong2 w0 = *(const ulonglong2*)(p.W4a + k*64 + f0);
            ulonglong2 w1 = *(const ulonglong2*)(p.W4a + k*64 + f0 + 4);
            acc[0] = fma2(aa, w0.x, acc[0]); acc[1] = fma2(aa, w0.y, acc[1]);
            acc[2] = fma2(aa, w1.x, acc[2]); acc[3] = fma2(aa, w1.y, acc[3]);
        }
        *(ulonglong2*)(bufA + n*68 + f0)     = make_ulonglong2(acc[0], acc[1]);
        *(ulonglong2*)(bufA + n*68 + f0 + 4) = make_ulonglong2(acc[2], acc[3]);
    }
    __syncthreads();
    {   // t2 = t1 @ W4b + b4b : [32][32] into bufB (stride 36), packed
        const int n = tid >> 3, f0 = (tid & 7) << 2;
        ull a01 = *(const ull*)(p.b4b + f0);
        ull a23 = *(const ull*)(p.b4b + f0 + 2);
        const float* r = bufA + n*68;
        #pragma unroll 4
        for (int k = 0; k < 64; ++k) {
            ull aa = dup2(r[k]);
            ulonglong2 w2 = *(const ulonglong2*)(p.W4b + k*32 + f0);
            a01 = fma2(aa, w2.x, a01);
            a23 = fma2(aa, w2.y, a23);
        }
        *(ulonglong2*)(bufB + n*36 + f0) = make_ulonglong2(a01, a23);
    }
    __syncthreads();
    {   // t3 = t2 @ W4c + b4c : [32][32] into bufA (stride 36), packed
        const int n = tid >> 3, f0 = (tid & 7) << 2;
        ull a01 = *(const ull*)(p.b4c + f0);
        ull a23 = *(const ull*)(p.b4c + f0 + 2);
        const float* r = bufB + n*36;
        #pragma unroll 4
        for (int k = 0; k < 32; ++k) {
            ull aa = dup2(r[k]);
            ulonglong2 w2 = *(const ulonglong2*)(p.W4c + k*32 + f0);
            a01 = fma2(aa, w2.x, a01);
            a23 = fma2(aa, w2.y, a23);
        }
        *(ulonglong2*)(bufA + n*36 + f0) = make_ulonglong2(a01, a23);
    }
    __syncthreads();
    {   // t4 = t3 @ W5a + b5a : [32][16] into bufB (stride 18)
        const int n = tid >> 3, f0 = (tid & 7) << 1;
        float a0 = p.b5a[f0], a1 = p.b5a[f0 + 1];
        const float* r = bufA + n*36;
        #pragma unroll 8
        for (int k = 0; k < 32; ++k) {
            float a = r[k];
            a0 += a * p.W5a[k*16 + f0];
            a1 += a * p.W5a[k*16 + f0 + 1];
        }
        bufB[n*18 + f0]     = a0;
        bufB[n*18 + f0 + 1] = a1;
    }
    __syncthreads();
    if (tid < 64) {
        const int n = tid >> 1, col = tid & 1;
        float acc = p.b5b[col];
        const float* r = bufB + n*18;
        #pragma unroll
        for (int k = 0; k < 16; ++k) acc += r[k] * p.W5b[k*2 + col];
        if (col == 0) p.out[b*32 + n] = acc;
        else          p.out[32768 + b*32 + n] = 1.0f / acc;
    }
}

extern "C" void kernel_launch(void* const* d_in, const int* in_sizes, int n_in,
                              void* d_out, int out_size) {
    const int has_iter = (n_in >= 32) ? 1 : 0;
    const int base = has_iter ? 8 : 7;

    GnnParams p;
    p.node0 = (const float*)d_in[0];
    p.edge  = (const float*)d_in[1];
    p.h0    = (const float*)d_in[2];
    p.mean  = (const float*)d_in[3];
    p.vari  = (const float*)d_in[4];
    p.iterp = has_iter ? (const int*)d_in[7] : nullptr;
    p.W1a = (const float*)d_in[base+0];  p.b1a = (const float*)d_in[base+1];
    p.W2a = (const float*)d_in[base+2];  p.b2a = (const float*)d_in[base+3];
    p.W2b = (const float*)d_in[base+4];  p.b2b = (const float*)d_in[base+5];
    p.W2c = (const float*)d_in[base+6];  p.b2c = (const float*)d_in[base+7];
    p.Wih = (const float*)d_in[base+8];  p.Whh = (const float*)d_in[base+9];
    p.bih = (const float*)d_in[base+10]; p.bhh = (const float*)d_in[base+11];
    p.W3b = (const float*)d_in[base+12]; p.b3b = (const float*)d_in[base+13];
    p.W4a = (const float*)d_in[base+14]; p.b4a = (const float*)d_in[base+15];
    p.W4b = (const float*)d_in[base+16]; p.b4b = (const float*)d_in[base+17];
    p.W4c = (const float*)d_in[base+18]; p.b4c = (const float*)d_in[base+19];
    p.W5a = (const float*)d_in[base+20]; p.b5a = (const float*)d_in[base+21];
    p.W5b = (const float*)d_in[base+22]; p.b5b = (const float*)d_in[base+23];
    p.out = (float*)d_out;

    cudaFuncSetAttribute(gnn_kernel,
                         cudaFuncAttributeMaxDynamicSharedMemorySize,
                         SMEM_FLOATS * (int)sizeof(float));
    gnn_kernel<<<1024, NT, SMEM_FLOATS * sizeof(float)>>>(p);
}